// round 16
// baseline (speedup 1.0000x reference)
#include <cuda_runtime.h>
#include <cstdint>
#include <cstddef>

// ---------------------------------------------------------------------------
// Lfm2ShortConv (sm_103 legacy-tensor path).
//   BCx = hidden @ W_in^T        GEMM1  8192x6144x2048
//   y   = C * conv3(B*x)         fused elementwise
//   out = y @ W_out^T            GEMM2  8192x2048x2048 (split-K=2 + reduce)
// R8: tile-major operands + cp.async.bulk feed -> 1548us.
// R9: full/empty mbarrier pipeline -> 1457us.
// R13: rotating producer warp -> 1384us (GEMM1 949us, tensor 71%).
// R14: GEMM2 split-K=2 (kills 13.5% wave-quantization tail) + A/B bulk
// copies issued by two different warps (full[] arrive-count 2).
// ---------------------------------------------------------------------------

#define SEQ  4096
#define HD   2048
#define MTOT 8192
#define KD   2048
#define NN1  6144
#define NN2  2048

// Scratch (__device__ globals: allocation-free rule), tile-major images
__device__ float g_hidT [(size_t)MTOT * KD];   // A1: 128-row tiles
__device__ float g_winT [(size_t)NN1  * KD];   // B1: 256-row tiles
__device__ float g_woutT[(size_t)NN2  * KD];   // B2: 256-row tiles
__device__ float g_yT   [(size_t)MTOT * KD];   // A2: 128-row tiles
__device__ float g_BCx  [(size_t)MTOT * NN1];  // GEMM1 out / GEMM2 partials

// ---- GEMM tiling ----------------------------------------------------------
constexpr int BM = 128, BN = 256, BK = 32;
constexpr int NTHREADS = 512;                  // 16 warps: 2 (M) x 8 (N)
constexpr int WM_ = 64, WN_ = 32;
constexpr int MT = WM_ / 16;                   // 4
constexpr int NT = WN_ / 8;                    // 4
constexpr int KTILES = KD / BK;                // 64 (full-K image stride)
constexpr int NSTAGE = 4;
constexpr uint32_t A_TILE_B = BM * BK * 4;     // 16384
constexpr uint32_t B_TILE_B = BN * BK * 4;     // 32768
constexpr uint32_t STAGE_B  = A_TILE_B + B_TILE_B;       // 49152
constexpr uint32_t BARS_OFF = NSTAGE * STAGE_B;          // 196608
constexpr uint32_t SMEM_DYN = BARS_OFF + 16 * NSTAGE;    // full[4] + empty[4]

// ---- PTX helpers ----------------------------------------------------------
__device__ __forceinline__ uint32_t smem_u32(const void* p) {
    uint32_t a;
    asm("{ .reg .u64 t; cvta.to.shared.u64 t, %1; cvt.u32.u64 %0, t; }" : "=r"(a) : "l"(p));
    return a;
}
__device__ __forceinline__ uint32_t f2tf(float f) {
    uint32_t u; asm("cvt.rna.tf32.f32 %0, %1;" : "=r"(u) : "f"(f)); return u;
}
__device__ __forceinline__ void bulk_g2s(uint32_t dst, const void* src,
                                         uint32_t bytes, uint32_t bar) {
    asm volatile(
        "cp.async.bulk.shared::cluster.global.mbarrier::complete_tx::bytes "
        "[%0], [%1], %2, [%3];"
        :: "r"(dst), "l"(src), "r"(bytes), "r"(bar) : "memory");
}
#define MBAR_INIT(a, c) \
    asm volatile("mbarrier.init.shared.b64 [%0], %1;" :: "r"(a), "r"(c) : "memory")
#define MBAR_EXPECT_TX(a, b) \
    asm volatile("mbarrier.arrive.expect_tx.shared.b64 _, [%0], %1;" :: "r"(a), "r"(b) : "memory")
#define MBAR_ARRIVE(a) \
    asm volatile("mbarrier.arrive.release.cta.shared.b64 _, [%0];" :: "r"(a) : "memory")
#define FENCE_PROXY_ASYNC() asm volatile("fence.proxy.async.shared::cta;" ::: "memory")
#define MBAR_WAIT(mbar, parity) do {                                          \
    uint32_t _m = (uint32_t)(mbar); uint32_t _p = (uint32_t)(parity);         \
    asm volatile(                                                             \
        "{\n\t.reg .pred P1;\n\t"                                             \
        "WL_%=:\n\t"                                                          \
        "mbarrier.try_wait.parity.acquire.cta.shared::cta.b64 P1, [%0], %1, 0x989680;\n\t" \
        "@P1 bra.uni WD_%=;\n\t"                                              \
        "bra.uni WL_%=;\n\t"                                                  \
        "WD_%=:\n\t}"                                                         \
        :: "r"(_m), "r"(_p) : "memory");                                      \
} while (0)

__device__ __forceinline__ void mma_tf32(float* c, const uint32_t* a, const uint32_t* b) {
    asm volatile(
        "mma.sync.aligned.m16n8k8.row.col.f32.tf32.tf32.f32 "
        "{%0,%1,%2,%3}, {%4,%5,%6,%7}, {%8,%9}, {%0,%1,%2,%3};\n"
        : "+f"(c[0]), "+f"(c[1]), "+f"(c[2]), "+f"(c[3])
        : "r"(a[0]), "r"(a[1]), "r"(a[2]), "r"(a[3]), "r"(b[0]), "r"(b[1]));
}

// ---- TN GEMM: C[M,N] = A[M,K] * B[N,K]^T over k-tiles [kt0, kt0+kcnt) -----
// Tile-major operands (full-K stride KTILES). blockIdx.z selects k-split;
// C points at the partial buffer for this split (caller adds offset via zstride).
__global__ void __launch_bounds__(NTHREADS, 1)
gemm_bulk(const float* __restrict__ At, const float* __restrict__ Bt,
          float* __restrict__ C, int N, int kcnt, size_t zstride)
{
    extern __shared__ char smc[];
    float* smf = (float*)smc;
    const uint32_t base = smem_u32(smc);
    const uint32_t fullb = base + BARS_OFF;          // full[s] at +8s
    const uint32_t emptb = fullb + 8 * NSTAGE;       // empty[s] at +8s

    const int tid  = threadIdx.x;
    const int lane = tid & 31;
    const int warp = tid >> 5;
    const int wm = (warp >> 3) * WM_;          // 0 or 64
    const int wn = (warp & 7)  * WN_;          // 0,32,...,224
    const int g  = lane >> 2;                  // 0..7
    const int c  = lane & 3;                   // 0..3
    const int kt0 = (int)blockIdx.z * kcnt;

    if (tid == 0) {
        #pragma unroll
        for (int s = 0; s < NSTAGE; s++) {
            MBAR_INIT(fullb + 8 * s, 2u);      // two expect_tx arrivals (A + B)
            MBAR_INIT(emptb + 8 * s, 16u);     // one arrive per warp
        }
        FENCE_PROXY_ASYNC();
    }
    __syncthreads();

    const float* Abase = At + ((size_t)blockIdx.y * KTILES + kt0) * (BM * BK);
    const float* Bbase = Bt + ((size_t)blockIdx.x * KTILES + kt0) * (BN * BK);

    // A copy for stage of ktile kt
    auto fillA = [&](int kt) {
        const int s = kt & 3;
        const uint32_t bar = fullb + 8 * s;
        MBAR_EXPECT_TX(bar, A_TILE_B);
        bulk_g2s(base + (uint32_t)s * STAGE_B,
                 Abase + (size_t)kt * (BM * BK), A_TILE_B, bar);
    };
    auto fillB = [&](int kt) {
        const int s = kt & 3;
        const uint32_t bar = fullb + 8 * s;
        MBAR_EXPECT_TX(bar, B_TILE_B);
        bulk_g2s(base + (uint32_t)s * STAGE_B + A_TILE_B,
                 Bbase + (size_t)kt * (BN * BK), B_TILE_B, bar);
    };

    // prologue: stages 0..2 — A by warps 0..2, B by warps 4..6 (lane 0)
    if (lane == 0) {
        #pragma unroll
        for (int k = 0; k < 3; k++) {
            if (k < kcnt) {
                if (warp == k)     fillA(k);
                if (warp == 4 + k) fillB(k);
            }
        }
    }

    float acc[MT][NT][4];
    #pragma unroll
    for (int i = 0; i < MT; i++)
        #pragma unroll
        for (int j = 0; j < NT; j++)
            #pragma unroll
            for (int q = 0; q < 4; q++) acc[i][j][q] = 0.f;

    for (int kt = 0; kt < kcnt; ++kt) {
        const int st = kt & 3;
        MBAR_WAIT(fullb + 8 * st, (kt >> 2) & 1);

        const float* as = smf + st * (STAGE_B / 4);
        const float* bs = as + (A_TILE_B / 4);

        // stored layout per tile row: 32 floats = 8 x 16B atoms; atom for
        // (c,h) is (2c+h) ^ (row&7); floats map k = 16h + 4j + c (j=0..3)
        #pragma unroll
        for (int h = 0; h < 2; ++h) {
            const int at = 2 * c + h;
            float4 bf[NT];
            #pragma unroll
            for (int ni = 0; ni < NT; ++ni) {
                const int r = wn + ni * 8 + g;
                bf[ni] = *(const float4*)(bs + r * 32 + ((at ^ g) << 2));
            }
            #pragma unroll
            for (int mi = 0; mi < MT; ++mi) {
                const int r0 = wm + mi * 16 + g;
                float4 a_lo = *(const float4*)(as + r0 * 32 + ((at ^ g) << 2));
                float4 a_hi = *(const float4*)(as + (r0 + 8) * 32 + ((at ^ g) << 2));
                const float* alo = &a_lo.x;
                const float* ahi = &a_hi.x;
                #pragma unroll
                for (int k2 = 0; k2 < 2; ++k2) {
                    uint32_t af[4];
                    af[0] = __float_as_uint(alo[2 * k2 + 0]);
                    af[1] = __float_as_uint(ahi[2 * k2 + 0]);
                    af[2] = __float_as_uint(alo[2 * k2 + 1]);
                    af[3] = __float_as_uint(ahi[2 * k2 + 1]);
                    #pragma unroll
                    for (int ni = 0; ni < NT; ++ni) {
                        const float* bp = &bf[ni].x;
                        uint32_t bfr[2];
                        bfr[0] = __float_as_uint(bp[2 * k2 + 0]);
                        bfr[1] = __float_as_uint(bp[2 * k2 + 1]);
                        mma_tf32(acc[mi][ni], af, bfr);
                    }
                }
            }
        }

        // this warp done with stage st
        if (lane == 0) MBAR_ARRIVE(emptb + 8 * st);

        // rotating dual producers: stage (kt+3): A by warp fk&3, B by 4+(fk&3)
        const int fk = kt + 3;
        if (fk < kcnt && lane == 0) {
            if (warp == (fk & 3)) {
                if (fk >= NSTAGE)
                    MBAR_WAIT(emptb + 8 * (fk & 3), ((fk >> 2) + 1) & 1);
                fillA(fk);
            } else if (warp == 4 + (fk & 3)) {
                if (fk >= NSTAGE)
                    MBAR_WAIT(emptb + 8 * (fk & 3), ((fk >> 2) + 1) & 1);
                fillB(fk);
            }
        }
    }

    // Epilogue: c0=(g,2c) c1=(g,2c+1) c2=(g+8,2c) c3=(g+8,2c+1)
    float* Cz = C + (size_t)blockIdx.z * zstride;
    const int brow = blockIdx.y * BM;
    const int bcol = blockIdx.x * BN;
    #pragma unroll
    for (int mi = 0; mi < MT; ++mi) {
        const int r0 = brow + wm + mi * 16 + g;
        #pragma unroll
        for (int ni = 0; ni < NT; ++ni) {
            const int cc = bcol + wn + ni * 8 + 2 * c;
            *reinterpret_cast<float2*>(Cz + (size_t)r0 * N + cc) =
                make_float2(acc[mi][ni][0], acc[mi][ni][1]);
            *reinterpret_cast<float2*>(Cz + (size_t)(r0 + 8) * N + cc) =
                make_float2(acc[mi][ni][2], acc[mi][ni][3]);
        }
    }
}

// ---- split-K reduce: out = p0 + p1 (float4) -------------------------------
__global__ void __launch_bounds__(256)
reduce2_k(const float4* __restrict__ p0, const float4* __restrict__ p1,
          float4* __restrict__ out, int n4)
{
    for (int i = blockIdx.x * blockDim.x + threadIdx.x; i < n4; i += gridDim.x * blockDim.x) {
        float4 a = p0[i], b = p1[i];
        out[i] = make_float4(a.x + b.x, a.y + b.y, a.z + b.z, a.w + b.w);
    }
}

// ---- prep: fp32 [R,2048] -> tf32-rounded tile-major (TH rows/tile) --------
__global__ void __launch_bounds__(256)
prep_tiles(const float4* __restrict__ in, float* __restrict__ out, int n4, int TH)
{
    for (int i = blockIdx.x * blockDim.x + threadIdx.x; i < n4; i += gridDim.x * blockDim.x) {
        float4 v = in[i];
        const int e = i * 4;
        const int r = e >> 11;
        const int k = e & 2047;
        const int rr = r % TH;
        const int q  = (k & 31) >> 2;
        float* tb = out + ((size_t)(r / TH) * KTILES + (k >> 5)) * ((size_t)TH * 32)
                  + rr * 32;
        const int sw = rr & 7;
        const int qa = q >> 2, qb = q & 3;
        tb[(((0 + qa) ^ sw) << 2) + qb] = __uint_as_float(f2tf(v.x));
        tb[(((2 + qa) ^ sw) << 2) + qb] = __uint_as_float(f2tf(v.y));
        tb[(((4 + qa) ^ sw) << 2) + qb] = __uint_as_float(f2tf(v.z));
        tb[(((6 + qa) ^ sw) << 2) + qb] = __uint_as_float(f2tf(v.w));
    }
}

// ---- conv + gating (float4: 4 channels/thread); y -> 128-row tile-major ---
__global__ void __launch_bounds__(256)
conv_gate_kernel(const float* __restrict__ BCx, const float* __restrict__ w,
                 float* __restrict__ yT)
{
    const int t = blockIdx.x * blockDim.x + threadIdx.x;     // < 8192*512
    const int h = (t << 2) & (HD - 1);                       // 4-aligned channel
    const int m = t >> 9;
    const int s = m & (SEQ - 1);

    const float* row = BCx + (size_t)m * NN1 + h;
    const float4 B0 = *(const float4*)(row);
    const float4 C0 = *(const float4*)(row + HD);
    const float4 X0 = *(const float4*)(row + 2 * HD);
    const float4 w0 = *(const float4*)(w + h * 3);
    const float4 w1 = *(const float4*)(w + h * 3 + 4);
    const float4 w2 = *(const float4*)(w + h * 3 + 8);

    float acc0 = w0.z * (B0.x * X0.x);
    float acc1 = w1.y * (B0.y * X0.y);
    float acc2 = w2.x * (B0.z * X0.z);
    float acc3 = w2.w * (B0.w * X0.w);
    if (s >= 1) {
        const float* r1 = row - NN1;
        const float4 B1 = *(const float4*)(r1);
        const float4 X1 = *(const float4*)(r1 + 2 * HD);
        acc0 += w0.y * (B1.x * X1.x);
        acc1 += w1.x * (B1.y * X1.y);
        acc2 += w1.w * (B1.z * X1.z);
        acc3 += w2.z * (B1.w * X1.w);
    }
    if (s >= 2) {
        const float* r2 = row - 2 * NN1;
        const float4 B2 = *(const float4*)(r2);
        const float4 X2 = *(const float4*)(r2 + 2 * HD);
        acc0 += w0.x * (B2.x * X2.x);
        acc1 += w0.w * (B2.y * X2.y);
        acc2 += w1.z * (B2.z * X2.z);
        acc3 += w2.y * (B2.w * X2.w);
    }
    acc0 *= C0.x; acc1 *= C0.y; acc2 *= C0.z; acc3 *= C0.w;

    const int rr = m & 127;
    const int sw = rr & 7;
    const int q  = (h & 31) >> 2;
    const int qa = q >> 2, qb = q & 3;
    float* tb = yT + ((size_t)(m >> 7) * KTILES + (h >> 5)) * (size_t)(128 * 32)
              + rr * 32;
    tb[(((0 + qa) ^ sw) << 2) + qb] = __uint_as_float(f2tf(acc0));
    tb[(((2 + qa) ^ sw) << 2) + qb] = __uint_as_float(f2tf(acc1));
    tb[(((4 + qa) ^ sw) << 2) + qb] = __uint_as_float(f2tf(acc2));
    tb[(((6 + qa) ^ sw) << 2) + qb] = __uint_as_float(f2tf(acc3));
}

// ---------------------------------------------------------------------------
extern "C" void kernel_launch(void* const* d_in, const int* in_sizes, int n_in,
                              void* d_out, int out_size)
{
    const float* hs    = (const float*)d_in[0];   // [2,4096,2048]
    const float* Win   = (const float*)d_in[1];   // [6144,2048]
    const float* convw = (const float*)d_in[2];   // [2048,1,3]
    const float* Wout  = (const float*)d_in[3];   // [2048,2048]
    float* out = (float*)d_out;

    float *hidT, *winT, *woutT, *yT, *bcx;
    cudaGetSymbolAddress((void**)&hidT,  g_hidT);
    cudaGetSymbolAddress((void**)&winT,  g_winT);
    cudaGetSymbolAddress((void**)&woutT, g_woutT);
    cudaGetSymbolAddress((void**)&yT,    g_yT);
    cudaGetSymbolAddress((void**)&bcx,   g_BCx);

    cudaFuncSetAttribute(gemm_bulk,
                         cudaFuncAttributeMaxDynamicSharedMemorySize, SMEM_DYN);

    // prep: round to tf32 + tile-major/permuted/swizzled images
    prep_tiles<<<2048, 256>>>((const float4*)hs,   hidT,  MTOT * KD / 4, 128);
    prep_tiles<<<2048, 256>>>((const float4*)Win,  winT,  NN1  * KD / 4, 256);
    prep_tiles<<<2048, 256>>>((const float4*)Wout, woutT, NN2  * KD / 4, 256);

    // GEMM1: BCx = hidden @ W_in^T   [8192 x 6144], full K
    gemm_bulk<<<dim3(NN1 / BN, MTOT / BM, 1), NTHREADS, SMEM_DYN>>>(
        hidT, winT, bcx, NN1, KTILES, 0);

    // conv + gating -> yT (tile-major)
    conv_gate_kernel<<<(MTOT * HD / 4) / 256, 256>>>(bcx, convw, yT);

    // GEMM2 split-K=2: partials into bcx scratch (reused), then reduce
    gemm_bulk<<<dim3(NN2 / BN, MTOT / BM, 2), NTHREADS, SMEM_DYN>>>(
        yT, woutT, bcx, NN2, KTILES / 2, (size_t)MTOT * NN2);
    reduce2_k<<<2048, 256>>>((const float4*)bcx,
                             (const float4*)(bcx + (size_t)MTOT * NN2),
                             (float4*)out, MTOT * NN2 / 4);
}